// round 14
// baseline (speedup 1.0000x reference)
#include <cuda_runtime.h>
#include <cuda_fp16.h>
#include <math_constants.h>
#include <cstdint>

#define Nn 64
#define Ll 1024
#define Hh 1024

// ---------------------------------------------------------------------------
// Device scratch
// ---------------------------------------------------------------------------
__device__ float g_dhP[8][Nn * Hh];
__device__ float g_scorePC[8][Nn * Ll];   // GLOBAL compact-row score partials
__device__ int   g_gidx[Nn * Ll];         // per-n local compact -> l
__device__ int   g_cnt[Nn];
__device__ int   g_off[Nn + 1];           // global row offsets (prefix of cnt)
__device__ __align__(16) __half g_Bh[Hh * Hh];
__device__ __align__(16) __half g_Ehc[Nn * Ll * Hh];  // GLOBAL compact fp16 E
__device__ float4 g_ctxP4[4][Nn * (Hh / 4)];

// ---------------------------------------------------------------------------
// Helpers
// ---------------------------------------------------------------------------
__device__ __forceinline__ uint32_t smem_u32(const void* p) {
    uint32_t a;
    asm("{ .reg .u64 t; cvta.to.shared.u64 t, %1; cvt.u32.u64 %0, t; }" : "=r"(a) : "l"(p));
    return a;
}
__device__ __forceinline__ float tanh_fast(float x) {
    float e = __expf(2.0f * x);
    return 1.0f - __fdividef(2.0f, e + 1.0f);
}
__device__ __forceinline__ void ldsm_x4(uint32_t* r, uint32_t addr) {
    asm volatile("ldmatrix.sync.aligned.m8n8.x4.shared.b16 {%0,%1,%2,%3}, [%4];"
                 : "=r"(r[0]), "=r"(r[1]), "=r"(r[2]), "=r"(r[3]) : "r"(addr));
}
__device__ __forceinline__ void mma_f16(float* c, const uint32_t* a, uint32_t b0, uint32_t b1) {
    asm volatile("mma.sync.aligned.m16n8k16.row.col.f32.f16.f16.f32 "
                 "{%0,%1,%2,%3}, {%4,%5,%6,%7}, {%8,%9}, {%0,%1,%2,%3};"
                 : "+f"(c[0]), "+f"(c[1]), "+f"(c[2]), "+f"(c[3])
                 : "r"(a[0]), "r"(a[1]), "r"(a[2]), "r"(a[3]), "r"(b0), "r"(b1));
}
__device__ __forceinline__ void cp_async16(uint32_t dst, const void* src) {
    asm volatile("cp.async.cg.shared.global [%0], [%1], 16;" :: "r"(dst), "l"(src) : "memory");
}

// ---- mbarrier ops (generic PTX) ----
#define MBAR_INIT(addr, cnt) \
    asm volatile("mbarrier.init.shared.b64 [%0], %1;" :: "r"((uint32_t)(addr)), "r"((uint32_t)(cnt)) : "memory")
#define MBAR_ARRIVE(addr) \
    asm volatile("{\n\t.reg .b64 t;\n\tmbarrier.arrive.shared.b64 t, [%0];\n\t}" \
                 :: "r"((uint32_t)(addr)) : "memory")
#define CP_ASYNC_MBAR_ARRIVE_NOINC(addr) \
    asm volatile("cp.async.mbarrier.arrive.noinc.shared.b64 [%0];" :: "r"((uint32_t)(addr)) : "memory")
#define MBAR_WAIT_PARITY(addr, parity) do {                                              \
    uint32_t _mbar = (uint32_t)(addr);                                                   \
    uint32_t _par  = (uint32_t)(parity);                                                 \
    uint32_t _done;                                                                      \
    asm volatile("{\n\t.reg .pred p;\n\t"                                                \
        "mbarrier.try_wait.parity.acquire.cta.shared::cta.b64 p, [%1], %2;\n\t"          \
        "selp.b32 %0, 1, 0, p;\n\t}" : "=r"(_done) : "r"(_mbar), "r"(_par) : "memory");  \
    if (!_done) {                                                                        \
        asm volatile("{\n\t.reg .pred P1;\n\t"                                           \
            "WL_%=:\n\t"                                                                 \
            "mbarrier.try_wait.parity.acquire.cta.shared::cta.b64 P1, [%0], %1, 0x989680;\n\t" \
            "@P1 bra.uni WD_%=;\n\t"                                                     \
            "bra.uni WL_%=;\n\t"                                                         \
            "WD_%=:\n\t}" :: "r"(_mbar), "r"(_par) : "memory");                          \
    }                                                                                    \
} while (0)

// ---------------------------------------------------------------------------
// Convert Ws -> fp16
// ---------------------------------------------------------------------------
__global__ __launch_bounds__(256) void bconv_kernel(const float* __restrict__ Ws) {
    size_t i = (size_t)blockIdx.x * 256 + threadIdx.x;
    float4 w0 = ((const float4*)Ws)[2 * i];
    float4 w1 = ((const float4*)Ws)[2 * i + 1];
    __half2 h[4];
    h[0] = __floats2half2_rn(w0.x, w0.y);
    h[1] = __floats2half2_rn(w0.z, w0.w);
    h[2] = __floats2half2_rn(w1.x, w1.y);
    h[3] = __floats2half2_rn(w1.z, w1.w);
    ((uint4*)g_Bh)[i] = *(uint4*)h;
}

// ---------------------------------------------------------------------------
// Compact kernel: per n, ordered unmasked l list; zero attn; counts.
// ---------------------------------------------------------------------------
__global__ __launch_bounds__(256) void compact_kernel(const int* __restrict__ mask,
                                                      float* __restrict__ attn) {
    __shared__ int sc[256];
    const int n = blockIdx.x;
    const int tid = threadIdx.x;
    int m[4];
    int c = 0;
#pragma unroll
    for (int q = 0; q < 4; ++q) {
        m[q] = mask[(n << 10) + tid * 4 + q];
        if (!m[q]) ++c;
        attn[(n << 10) + tid * 4 + q] = 0.f;
    }
    sc[tid] = c;
    __syncthreads();
    for (int off = 1; off < 256; off <<= 1) {
        int vv = (tid >= off) ? sc[tid - off] : 0;
        __syncthreads();
        sc[tid] += vv;
        __syncthreads();
    }
    int base = sc[tid] - c;
    if (tid == 255) g_cnt[n] = sc[255];
#pragma unroll
    for (int q = 0; q < 4; ++q)
        if (!m[q]) g_gidx[(n << 10) + base++] = tid * 4 + q;
}

// ---------------------------------------------------------------------------
// Prefix scan of counts -> global offsets (1 block, trivial)
// ---------------------------------------------------------------------------
__global__ void scan_kernel() {
    if (threadIdx.x == 0) {
        int acc = 0;
        for (int i = 0; i < Nn; ++i) {
            g_off[i] = acc;
            acc += g_cnt[i];
        }
        g_off[Nn] = acc;
    }
}

// ---------------------------------------------------------------------------
// Convert unmasked E rows -> GLOBALLY compact fp16 layout.
// ---------------------------------------------------------------------------
__global__ __launch_bounds__(256) void econvc_kernel(const float* __restrict__ E) {
    const int n = blockIdx.x;
    const int row0 = blockIdx.y * 128;
    const int cnt = g_cnt[n];
    if (row0 >= cnt) return;
    const int tid = threadIdx.x;
    const int lim = min(128, cnt - row0);
    const int gbase = g_off[n] + row0;
    for (int i = tid; i < 128 * 128; i += 256) {
        int r = i >> 7;
        if (r >= lim) break;
        int u = i & 127;
        int gl = g_gidx[(n << 10) + row0 + r];
        const float4* src = (const float4*)(E + ((size_t)(n << 10) + gl) * Hh) + u * 2;
        float4 w0 = src[0], w1 = src[1];
        __half2 h[4];
        h[0] = __floats2half2_rn(w0.x, w0.y);
        h[1] = __floats2half2_rn(w0.z, w0.w);
        h[2] = __floats2half2_rn(w1.x, w1.y);
        h[3] = __floats2half2_rn(w1.z, w1.w);
        ((uint4*)(g_Ehc + (size_t)(gbase + r) * Hh))[u] = *(uint4*)h;
    }
}

// ---------------------------------------------------------------------------
// dh partials: tiled GEMM. grid 128 = 16 k-blocks x 8 h-splits.
// ---------------------------------------------------------------------------
__global__ __launch_bounds__(256) void dh_kernel(const float* __restrict__ dec,
                                                 const float* __restrict__ Wh) {
    __shared__ float ds[64][68];
    __shared__ float ws[64][68];
    const int tid = threadIdx.x;
    const int kb = (blockIdx.x & 15) * 64;
    const int hs = blockIdx.x >> 4;
    const int n0 = (tid & 15) * 4;
    const int k0 = (tid >> 4) * 4;
    float acc[4][4] = {};
    for (int cc = 0; cc < 2; ++cc) {
        const int hb = hs * 128 + cc * 64;
        __syncthreads();
#pragma unroll
        for (int q = 0; q < 4; ++q) {
            int f4 = tid + 256 * q;
            int r = f4 >> 4;
            int col = f4 & 15;
            float4 a = *(const float4*)(dec + (size_t)r * Hh + hb + col * 4);
            ds[col * 4 + 0][r] = a.x; ds[col * 4 + 1][r] = a.y;
            ds[col * 4 + 2][r] = a.z; ds[col * 4 + 3][r] = a.w;
            float4 b = *(const float4*)(Wh + (size_t)(kb + r) * Hh + hb + col * 4);
            ws[col * 4 + 0][r] = b.x; ws[col * 4 + 1][r] = b.y;
            ws[col * 4 + 2][r] = b.z; ws[col * 4 + 3][r] = b.w;
        }
        __syncthreads();
#pragma unroll 8
        for (int h = 0; h < 64; ++h) {
            float a[4], b[4];
            *(float4*)a = *(const float4*)&ds[h][n0];
            *(float4*)b = *(const float4*)&ws[h][k0];
#pragma unroll
            for (int i = 0; i < 4; ++i)
#pragma unroll
                for (int j = 0; j < 4; ++j) acc[i][j] += a[i] * b[j];
        }
    }
#pragma unroll
    for (int i = 0; i < 4; ++i)
#pragma unroll
        for (int j = 0; j < 4; ++j)
            g_dhP[hs][(n0 + i) * Hh + kb + k0 + j] = acc[i][j];
}

__device__ __forceinline__ float dh_sum(int idx) {
    float a = 0.f;
#pragma unroll
    for (int p = 0; p < 8; ++p) a += g_dhP[p][idx];
    return a;
}

// ---------------------------------------------------------------------------
// Fused score kernel on GLOBAL compact rows. Tiles span <=2 n's; epilogue
// selects dh slice per accumulator row. grid (512 tiles, 2 j-halves).
// ---------------------------------------------------------------------------
#define A_BYTES 16384
#define STAGE_BYTES (2 * A_BYTES)
#define NSTAGE 3
#define SM_DH   0                  // 2 jbuf x (dh_n0 512B + dh_n1 512B)
#define SM_V    2048               // 2 jbuf x 512B
#define SM_SRED 3072
#define SM_MBAR 4096
#define SM_STG  5120
#define SM_TOTAL (SM_STG + NSTAGE * STAGE_BYTES)  // 103424

__global__ __launch_bounds__(256, 2) void score_kernel(const float* __restrict__ v) {
    const int row0c = blockIdx.x * 128;      // global compact row base
    if (row0c >= g_off[Nn]) return;

    extern __shared__ char smem[];
    const uint32_t sb = smem_u32(smem);
    const int tid = threadIdx.x;
    const int lane = tid & 31;
    const int wid = tid >> 5;
    const int wm = wid & 3;
    const int wn = wid >> 2;
    const int j0 = blockIdx.y * 4;

    // find n0 (first row) and n1 (last row); boundary = g_off[n1]
    int n0 = 0, n1 = 0;
    for (int m = 1; m < Nn; ++m) {
        int o = g_off[m];
        if (o <= row0c) n0 = m;
        if (o <= row0c + 127) n1 = m;
    }
    const int bl = g_off[n1] - row0c;        // rows >= bl belong to n1

    // ---- loader precompute (regular global-compact addressing) ----
    uint32_t ldst[4];
    size_t gaoff[4];
    uint32_t gboff_c[4];
#pragma unroll
    for (int t = 0; t < 4; ++t) {
        int u = tid + 256 * t;
        int lrow = u >> 3, lseg = u & 7;
        ldst[t] = (uint32_t)(lrow * 128 + ((lseg ^ (lrow & 7)) << 4));
        gaoff[t] = (size_t)(row0c + lrow) * Hh + lseg * 8;
        gboff_c[t] = (uint32_t)(lrow * Hh + lseg * 8);
    }

    // ---- ldsm address bases ----
    uint32_t abase[2], axr[2], bbase[4], bxr[4];
    {
        const int aseg0 = lane >> 4;
        const int bseg0 = (lane >> 3) & 1;
#pragma unroll
        for (int mt = 0; mt < 2; ++mt) {
            int r = wm * 32 + mt * 16 + (lane & 15);
            abase[mt] = (uint32_t)(r * 128 + ((aseg0 ^ (r & 1)) << 4));
            axr[mt] = (uint32_t)(r & 6);
        }
#pragma unroll
        for (int np = 0; np < 4; ++np) {
            int r = wn * 64 + np * 16 + ((lane >> 4) << 3) + (lane & 7);
            bbase[np] = (uint32_t)(r * 128 + ((bseg0 ^ (r & 1)) << 4));
            bxr[np] = (uint32_t)(r & 6);
        }
    }
    const uint32_t ksrot = (uint32_t)(wn << 1);

    auto fill = [&](int cc2) {
        const int s2 = cc2 % NSTAGE;
        const uint32_t base = sb + SM_STG + (uint32_t)s2 * STAGE_BYTES;
        const int kb = (cc2 & 15) * 64;
        const uint32_t jb = (uint32_t)((j0 + (cc2 >> 4)) * 128) * Hh;
#pragma unroll
        for (int t = 0; t < 4; ++t) cp_async16(base + ldst[t], g_Ehc + gaoff[t] + kb);
#pragma unroll
        for (int t = 0; t < 4; ++t)
            cp_async16(base + A_BYTES + ldst[t], g_Bh + jb + gboff_c[t] + kb);
        CP_ASYNC_MBAR_ARRIVE_NOINC(sb + SM_MBAR + s2 * 16);
    };

    if (tid == 0) {
#pragma unroll
        for (int s = 0; s < NSTAGE; ++s) {
            MBAR_INIT(sb + SM_MBAR + s * 16, 256);
            MBAR_INIT(sb + SM_MBAR + s * 16 + 8, 256);
        }
    }
    // dh slices for n0 (tid<128) and n1 (tid>=128); v by tid<128
    if (tid < 128) {
        ((float*)(smem + SM_DH))[tid] = dh_sum((n0 << 10) + j0 * 128 + tid);
        ((float*)(smem + SM_V))[tid] = v[j0 * 128 + tid];
    } else {
        ((float*)(smem + SM_DH))[tid] = dh_sum((n1 << 10) + j0 * 128 + (tid - 128));
    }
    __syncthreads();

    float acc[2][8][4];
#pragma unroll
    for (int mt = 0; mt < 2; ++mt)
#pragma unroll
        for (int nt = 0; nt < 8; ++nt)
#pragma unroll
            for (int e = 0; e < 4; ++e) acc[mt][nt][e] = 0.f;

    fill(0);
    fill(1);

    for (int cc = 0; cc < 64; ++cc) {
        const int s = cc % NSTAGE;
        MBAR_WAIT_PARITY(sb + SM_MBAR + s * 16, (cc / 3) & 1);

        const uint32_t base = sb + SM_STG + (uint32_t)s * STAGE_BYTES;
        const uint32_t sA = base;
        const uint32_t sB = base + A_BYTES;

#pragma unroll
        for (int ks = 0; ks < 4; ++ks) {
            const uint32_t ksx = (uint32_t)(((ks + ksrot) & 3) * 2);
            uint32_t ah[2][4];
            ldsm_x4(ah[0], sA + abase[0] + ((ksx ^ axr[0]) << 4));
            ldsm_x4(ah[1], sA + abase[1] + ((ksx ^ axr[1]) << 4));
            uint32_t bb[2][4];
            ldsm_x4(bb[0], sB + bbase[0] + ((ksx ^ bxr[0]) << 4));
#pragma unroll
            for (int np = 0; np < 4; ++np) {
                if (np < 3)
                    ldsm_x4(bb[(np + 1) & 1], sB + bbase[np + 1] + ((ksx ^ bxr[np + 1]) << 4));
                const uint32_t* bq = bb[np & 1];
                mma_f16(acc[0][np * 2 + 0], ah[0], bq[0], bq[1]);
                mma_f16(acc[0][np * 2 + 1], ah[0], bq[2], bq[3]);
                mma_f16(acc[1][np * 2 + 0], ah[1], bq[0], bq[1]);
                mma_f16(acc[1][np * 2 + 1], ah[1], bq[2], bq[3]);
            }
        }
        MBAR_ARRIVE(sb + SM_MBAR + s * 16 + 8);

        const int c2 = cc + 2;
        if (c2 < 64) {
            const int s2 = c2 % NSTAGE;
            if (c2 >= NSTAGE)
                MBAR_WAIT_PARITY(sb + SM_MBAR + s2 * 16 + 8, (c2 / 3 - 1) & 1);
            fill(c2);
        }

        if ((cc & 15) == 15) {
            const int jloc = cc >> 4;
            const int jglob = j0 + jloc;
            const int jb1 = jloc & 1;
            if (jloc < 3) {
                if (tid < 128) {
                    ((float*)(smem + SM_DH + (1 - jb1) * 1024))[tid] =
                        dh_sum((n0 << 10) + (jglob + 1) * 128 + tid);
                    ((float*)(smem + SM_V + (1 - jb1) * 512))[tid] =
                        v[(jglob + 1) * 128 + tid];
                } else {
                    ((float*)(smem + SM_DH + (1 - jb1) * 1024))[tid] =
                        dh_sum((n1 << 10) + (jglob + 1) * 128 + (tid - 128));
                }
            }
            const float* dhb = (const float*)(smem + SM_DH + jb1 * 1024);
            const float* vs = (const float*)(smem + SM_V + jb1 * 512);
            // per-accumulator-row dh slice selection (n0 vs n1)
            const float* dsel[2][2];
#pragma unroll
            for (int mt = 0; mt < 2; ++mt)
#pragma unroll
                for (int rh = 0; rh < 2; ++rh) {
                    int rl = wm * 32 + mt * 16 + (lane >> 2) + rh * 8;
                    dsel[mt][rh] = (rl >= bl) ? (dhb + 128) : dhb;
                }
            float part[4] = {0.f, 0.f, 0.f, 0.f};
#pragma unroll
            for (int mt = 0; mt < 2; ++mt)
#pragma unroll
                for (int nt = 0; nt < 8; ++nt)
#pragma unroll
                    for (int e = 0; e < 4; ++e) {
                        int col = wn * 64 + nt * 8 + (lane & 3) * 2 + (e & 1);
                        part[mt * 2 + (e >> 1)] +=
                            tanh_fast(acc[mt][nt][e] + dsel[mt][e >> 1][col]) * vs[col];
                        acc[mt][nt][e] = 0.f;
                    }
#pragma unroll
            for (int p = 0; p < 4; ++p) {
                part[p] += __shfl_xor_sync(0xffffffffu, part[p], 1);
                part[p] += __shfl_xor_sync(0xffffffffu, part[p], 2);
            }
            float* sred = (float*)(smem + SM_SRED);
            __syncthreads();
            if ((lane & 3) == 0) {
#pragma unroll
                for (int mt = 0; mt < 2; ++mt)
#pragma unroll
                    for (int rr = 0; rr < 2; ++rr) {
                        int row = wm * 32 + mt * 16 + (lane >> 2) + rr * 8;
                        sred[row * 2 + wn] = part[mt * 2 + rr];
                    }
            }
            __syncthreads();
            if (tid < 128)
                g_scorePC[jglob][row0c + tid] = sred[tid * 2] + sred[tid * 2 + 1];
        }
    }
}

// ---------------------------------------------------------------------------
// Context with inline softmax over GLOBAL compact rows of this n.
// ---------------------------------------------------------------------------
__global__ __launch_bounds__(128) void context_kernel(float* __restrict__ attn) {
    __shared__ float sa[256];
    __shared__ float red[128];
    const int n = blockIdx.x, lc = blockIdx.y;
    const int tid = threadIdx.x;
    const int cnt = g_cnt[n];
    const int gbase = g_off[n];

    float s[8];
    float pv[8];
    float lmax = -CUDART_INF_F;
#pragma unroll
    for (int q = 0; q < 8; ++q) {
        int r = tid + 128 * q;
        float a = 0.f;
        if (r < cnt) {
#pragma unroll
            for (int p = 0; p < 8; ++p) a += g_scorePC[p][gbase + r];
            lmax = fmaxf(lmax, a);
        }
        s[q] = a;
    }
    red[tid] = lmax;
    __syncthreads();
    for (int o = 64; o; o >>= 1) {
        if (tid < o) red[tid] = fmaxf(red[tid], red[tid + o]);
        __syncthreads();
    }
    const float mx = red[0];
    __syncthreads();
    float lsum = 0.f;
#pragma unroll
    for (int q = 0; q < 8; ++q) {
        int r = tid + 128 * q;
        pv[q] = (r < cnt) ? __expf(s[q] - mx) : 0.f;
        lsum += pv[q];
    }
    red[tid] = lsum;
    __syncthreads();
    for (int o = 64; o; o >>= 1) {
        if (tid < o) red[tid] += red[tid + o];
        __syncthreads();
    }
    const float inv = 1.0f / red[0];
    __syncthreads();

#pragma unroll
    for (int qq = 0; qq < 2; ++qq) {
        int q = 2 * lc + qq;
        int r = tid + 128 * q;
        int i = tid + 128 * qq;
        float w = 0.f;
        if (r < cnt) {
            int l = g_gidx[(n << 10) + r];
            w = pv[q] * inv;
            attn[(n << 10) + l] = w;
        }
        sa[i] = w;
    }
    __syncthreads();

    const int lim = min(256, cnt - lc * 256);
    const uint4* Ep = (const uint4*)(g_Ehc + (size_t)(gbase + lc * 256) * Hh) + tid;
    float acc[8] = {};
#pragma unroll 4
    for (int i = 0; i < lim; ++i) {
        uint4 u = Ep[(size_t)i * 128];
        const __half2* h2 = (const __half2*)&u;
        float a = sa[i];
#pragma unroll
        for (int q = 0; q < 4; ++q) {
            float2 f = __half22float2(h2[q]);
            acc[q * 2 + 0] += a * f.x;
            acc[q * 2 + 1] += a * f.y;
        }
    }
    float4* dst = &g_ctxP4[lc][n * 256 + tid * 2];
    dst[0] = make_float4(acc[0], acc[1], acc[2], acc[3]);
    dst[1] = make_float4(acc[4], acc[5], acc[6], acc[7]);
}

__global__ __launch_bounds__(256) void ctx_reduce_kernel(float4* __restrict__ ctx4) {
    int i = blockIdx.x * 256 + threadIdx.x;
    float4 a = g_ctxP4[0][i], b = g_ctxP4[1][i], c = g_ctxP4[2][i], d = g_ctxP4[3][i];
    ctx4[i] = make_float4(a.x + b.x + c.x + d.x, a.y + b.y + c.y + d.y,
                          a.z + b.z + c.z + d.z, a.w + b.w + c.w + d.w);
}

// ---------------------------------------------------------------------------
extern "C" void kernel_launch(void* const* d_in, const int* in_sizes, int n_in,
                              void* d_out, int out_size) {
    const float* dec  = (const float*)d_in[0];
    const float* E    = (const float*)d_in[1];
    const int*   mask = (const int*)  d_in[2];
    const float* Wh   = (const float*)d_in[3];
    const float* Ws   = (const float*)d_in[4];
    const float* v    = (const float*)d_in[5];

    float* out  = (float*)d_out;
    float* ctx  = out;
    float* attn = out + Nn * Hh;

    cudaFuncSetAttribute(score_kernel, cudaFuncAttributeMaxDynamicSharedMemorySize, SM_TOTAL);

    bconv_kernel<<<(Hh * Hh / 8) / 256, 256>>>(Ws);
    compact_kernel<<<Nn, 256>>>(mask, attn);
    scan_kernel<<<1, 32>>>();
    econvc_kernel<<<dim3(Nn, 8), 256>>>(E);
    dh_kernel<<<128, 256>>>(dec, Wh);
    score_kernel<<<dim3(512, 2), 256, SM_TOTAL>>>(v);
    context_kernel<<<dim3(Nn, 4), 128>>>(attn);
    ctx_reduce_kernel<<<(Nn * Hh / 4) / 256, 256>>>((float4*)ctx);
}

// round 15
// speedup vs baseline: 1.0674x; 1.0674x over previous
#include <cuda_runtime.h>
#include <cuda_fp16.h>
#include <math_constants.h>
#include <cstdint>

#define Nn 64
#define Ll 1024
#define Hh 1024

// ---------------------------------------------------------------------------
// Device scratch
// ---------------------------------------------------------------------------
__device__ float g_dhP[8][Nn * Hh];
__device__ float g_scorePC[8][Nn * Ll];   // GLOBAL compact-row score partials
__device__ int   g_gidx[Nn * Ll];         // per-n local compact -> l
__device__ int   g_cnt[Nn];
__device__ int   g_off[Nn + 1];           // global row offsets (prefix of cnt)
__device__ __align__(16) __half g_Bh[Hh * Hh];
__device__ __align__(16) __half g_Ehc[Nn * Ll * Hh];  // GLOBAL compact fp16 E
__device__ float4 g_ctxP4[4][Nn * (Hh / 4)];

// ---------------------------------------------------------------------------
// Helpers
// ---------------------------------------------------------------------------
__device__ __forceinline__ uint32_t smem_u32(const void* p) {
    uint32_t a;
    asm("{ .reg .u64 t; cvta.to.shared.u64 t, %1; cvt.u32.u64 %0, t; }" : "=r"(a) : "l"(p));
    return a;
}
__device__ __forceinline__ float tanh_fast(float x) {
    float e = __expf(2.0f * x);
    return 1.0f - __fdividef(2.0f, e + 1.0f);
}
__device__ __forceinline__ void ldsm_x4(uint32_t* r, uint32_t addr) {
    asm volatile("ldmatrix.sync.aligned.m8n8.x4.shared.b16 {%0,%1,%2,%3}, [%4];"
                 : "=r"(r[0]), "=r"(r[1]), "=r"(r[2]), "=r"(r[3]) : "r"(addr));
}
__device__ __forceinline__ void mma_f16(float* c, const uint32_t* a, uint32_t b0, uint32_t b1) {
    asm volatile("mma.sync.aligned.m16n8k16.row.col.f32.f16.f16.f32 "
                 "{%0,%1,%2,%3}, {%4,%5,%6,%7}, {%8,%9}, {%0,%1,%2,%3};"
                 : "+f"(c[0]), "+f"(c[1]), "+f"(c[2]), "+f"(c[3])
                 : "r"(a[0]), "r"(a[1]), "r"(a[2]), "r"(a[3]), "r"(b0), "r"(b1));
}
__device__ __forceinline__ void cp_async16(uint32_t dst, const void* src) {
    asm volatile("cp.async.cg.shared.global [%0], [%1], 16;" :: "r"(dst), "l"(src) : "memory");
}

// ---- mbarrier ops (generic PTX) ----
#define MBAR_INIT(addr, cnt) \
    asm volatile("mbarrier.init.shared.b64 [%0], %1;" :: "r"((uint32_t)(addr)), "r"((uint32_t)(cnt)) : "memory")
#define MBAR_ARRIVE(addr) \
    asm volatile("{\n\t.reg .b64 t;\n\tmbarrier.arrive.shared.b64 t, [%0];\n\t}" \
                 :: "r"((uint32_t)(addr)) : "memory")
#define CP_ASYNC_MBAR_ARRIVE_NOINC(addr) \
    asm volatile("cp.async.mbarrier.arrive.noinc.shared.b64 [%0];" :: "r"((uint32_t)(addr)) : "memory")
#define MBAR_WAIT_PARITY(addr, parity) do {                                              \
    uint32_t _mbar = (uint32_t)(addr);                                                   \
    uint32_t _par  = (uint32_t)(parity);                                                 \
    uint32_t _done;                                                                      \
    asm volatile("{\n\t.reg .pred p;\n\t"                                                \
        "mbarrier.try_wait.parity.acquire.cta.shared::cta.b64 p, [%1], %2;\n\t"          \
        "selp.b32 %0, 1, 0, p;\n\t}" : "=r"(_done) : "r"(_mbar), "r"(_par) : "memory");  \
    if (!_done) {                                                                        \
        asm volatile("{\n\t.reg .pred P1;\n\t"                                           \
            "WL_%=:\n\t"                                                                 \
            "mbarrier.try_wait.parity.acquire.cta.shared::cta.b64 P1, [%0], %1, 0x989680;\n\t" \
            "@P1 bra.uni WD_%=;\n\t"                                                     \
            "bra.uni WL_%=;\n\t"                                                         \
            "WD_%=:\n\t}" :: "r"(_mbar), "r"(_par) : "memory");                          \
    }                                                                                    \
} while (0)

// ---------------------------------------------------------------------------
// Convert Ws -> fp16
// ---------------------------------------------------------------------------
__global__ __launch_bounds__(256) void bconv_kernel(const float* __restrict__ Ws) {
    size_t i = (size_t)blockIdx.x * 256 + threadIdx.x;
    float4 w0 = ((const float4*)Ws)[2 * i];
    float4 w1 = ((const float4*)Ws)[2 * i + 1];
    __half2 h[4];
    h[0] = __floats2half2_rn(w0.x, w0.y);
    h[1] = __floats2half2_rn(w0.z, w0.w);
    h[2] = __floats2half2_rn(w1.x, w1.y);
    h[3] = __floats2half2_rn(w1.z, w1.w);
    ((uint4*)g_Bh)[i] = *(uint4*)h;
}

// ---------------------------------------------------------------------------
// Compact kernel: per n, ordered unmasked l list; zero attn; counts.
// ---------------------------------------------------------------------------
__global__ __launch_bounds__(256) void compact_kernel(const int* __restrict__ mask,
                                                      float* __restrict__ attn) {
    __shared__ int sc[256];
    const int n = blockIdx.x;
    const int tid = threadIdx.x;
    int m[4];
    int c = 0;
#pragma unroll
    for (int q = 0; q < 4; ++q) {
        m[q] = mask[(n << 10) + tid * 4 + q];
        if (!m[q]) ++c;
        attn[(n << 10) + tid * 4 + q] = 0.f;
    }
    sc[tid] = c;
    __syncthreads();
    for (int off = 1; off < 256; off <<= 1) {
        int vv = (tid >= off) ? sc[tid - off] : 0;
        __syncthreads();
        sc[tid] += vv;
        __syncthreads();
    }
    int base = sc[tid] - c;
    if (tid == 255) g_cnt[n] = sc[255];
#pragma unroll
    for (int q = 0; q < 4; ++q)
        if (!m[q]) g_gidx[(n << 10) + base++] = tid * 4 + q;
}

// ---------------------------------------------------------------------------
// Prefix scan of counts -> global offsets
// ---------------------------------------------------------------------------
__global__ void scan_kernel() {
    if (threadIdx.x == 0) {
        int acc = 0;
        for (int i = 0; i < Nn; ++i) {
            g_off[i] = acc;
            acc += g_cnt[i];
        }
        g_off[Nn] = acc;
    }
}

// ---------------------------------------------------------------------------
// Convert unmasked E rows -> GLOBAL compact fp16. Row indices staged in smem;
// copy loop unrolled x4 (8 independent float4 loads in flight).
// ---------------------------------------------------------------------------
__global__ __launch_bounds__(256) void econvc_kernel(const float* __restrict__ E) {
    __shared__ int sgl[128];
    const int n = blockIdx.x;
    const int row0 = blockIdx.y * 128;
    const int cnt = g_cnt[n];
    if (row0 >= cnt) return;
    const int tid = threadIdx.x;
    const int lim = min(128, cnt - row0);
    const int gbase = g_off[n] + row0;

    if (tid < 128)
        sgl[tid] = (tid < lim) ? g_gidx[(n << 10) + row0 + tid] : 0;
    __syncthreads();

    const int u = tid & 127;          // uint4 col (fixed per thread)
    const int r0 = tid >> 7;          // starting row (0 or 1), stride 2
    const float4* __restrict__ Ebase = (const float4*)(E + (size_t)(n << 10) * Hh);

#pragma unroll 1
    for (int k = 0; k < 64; k += 4) {
        int rr[4];
        float4 w0[4], w1[4];
#pragma unroll
        for (int q = 0; q < 4; ++q) {
            rr[q] = r0 + 2 * (k + q);
            if (rr[q] < lim) {
                const float4* src = Ebase + (size_t)sgl[rr[q]] * 256 + u * 2;
                w0[q] = src[0];
                w1[q] = src[1];
            }
        }
#pragma unroll
        for (int q = 0; q < 4; ++q) {
            if (rr[q] < lim) {
                __half2 h[4];
                h[0] = __floats2half2_rn(w0[q].x, w0[q].y);
                h[1] = __floats2half2_rn(w0[q].z, w0[q].w);
                h[2] = __floats2half2_rn(w1[q].x, w1[q].y);
                h[3] = __floats2half2_rn(w1[q].z, w1[q].w);
                ((uint4*)(g_Ehc + (size_t)(gbase + rr[q]) * Hh))[u] = *(uint4*)h;
            }
        }
    }
}

// ---------------------------------------------------------------------------
// dh partials: tiled GEMM. grid 128 = 16 k-blocks x 8 h-splits.
// ---------------------------------------------------------------------------
__global__ __launch_bounds__(256) void dh_kernel(const float* __restrict__ dec,
                                                 const float* __restrict__ Wh) {
    __shared__ float ds[64][68];
    __shared__ float ws[64][68];
    const int tid = threadIdx.x;
    const int kb = (blockIdx.x & 15) * 64;
    const int hs = blockIdx.x >> 4;
    const int n0 = (tid & 15) * 4;
    const int k0 = (tid >> 4) * 4;
    float acc[4][4] = {};
    for (int cc = 0; cc < 2; ++cc) {
        const int hb = hs * 128 + cc * 64;
        __syncthreads();
#pragma unroll
        for (int q = 0; q < 4; ++q) {
            int f4 = tid + 256 * q;
            int r = f4 >> 4;
            int col = f4 & 15;
            float4 a = *(const float4*)(dec + (size_t)r * Hh + hb + col * 4);
            ds[col * 4 + 0][r] = a.x; ds[col * 4 + 1][r] = a.y;
            ds[col * 4 + 2][r] = a.z; ds[col * 4 + 3][r] = a.w;
            float4 b = *(const float4*)(Wh + (size_t)(kb + r) * Hh + hb + col * 4);
            ws[col * 4 + 0][r] = b.x; ws[col * 4 + 1][r] = b.y;
            ws[col * 4 + 2][r] = b.z; ws[col * 4 + 3][r] = b.w;
        }
        __syncthreads();
#pragma unroll 8
        for (int h = 0; h < 64; ++h) {
            float a[4], b[4];
            *(float4*)a = *(const float4*)&ds[h][n0];
            *(float4*)b = *(const float4*)&ws[h][k0];
#pragma unroll
            for (int i = 0; i < 4; ++i)
#pragma unroll
                for (int j = 0; j < 4; ++j) acc[i][j] += a[i] * b[j];
        }
    }
#pragma unroll
    for (int i = 0; i < 4; ++i)
#pragma unroll
        for (int j = 0; j < 4; ++j)
            g_dhP[hs][(n0 + i) * Hh + kb + k0 + j] = acc[i][j];
}

__device__ __forceinline__ float dh_sum(int idx) {
    float a = 0.f;
#pragma unroll
    for (int p = 0; p < 8; ++p) a += g_dhP[p][idx];
    return a;
}

// ---------------------------------------------------------------------------
// Fused score kernel on GLOBAL compact rows, ALL 8 j-blocks per CTA
// (cc = 0..127; A read once). Tiles span <=2 n's. grid 512 tiles, early exit.
// ---------------------------------------------------------------------------
#define A_BYTES 16384
#define STAGE_BYTES (2 * A_BYTES)
#define NSTAGE 3
#define SM_DH   0                  // 2 jbuf x (dh_n0 512B + dh_n1 512B)
#define SM_V    2048               // 2 jbuf x 512B
#define SM_SRED 3072
#define SM_MBAR 4096
#define SM_STG  5120
#define SM_TOTAL (SM_STG + NSTAGE * STAGE_BYTES)  // 103424

__global__ __launch_bounds__(256, 2) void score_kernel(const float* __restrict__ v) {
    const int row0c = blockIdx.x * 128;
    if (row0c >= g_off[Nn]) return;

    extern __shared__ char smem[];
    const uint32_t sb = smem_u32(smem);
    const int tid = threadIdx.x;
    const int lane = tid & 31;
    const int wid = tid >> 5;
    const int wm = wid & 3;
    const int wn = wid >> 2;

    // find n0/n1 and boundary
    int n0 = 0, n1 = 0;
    for (int m = 1; m < Nn; ++m) {
        int o = g_off[m];
        if (o <= row0c) n0 = m;
        if (o <= row0c + 127) n1 = m;
    }
    const int bl = g_off[n1] - row0c;

    // ---- loader precompute ----
    uint32_t ldst[4];
    size_t gaoff[4];
    uint32_t gboff_c[4];
#pragma unroll
    for (int t = 0; t < 4; ++t) {
        int u = tid + 256 * t;
        int lrow = u >> 3, lseg = u & 7;
        ldst[t] = (uint32_t)(lrow * 128 + ((lseg ^ (lrow & 7)) << 4));
        gaoff[t] = (size_t)(row0c + lrow) * Hh + lseg * 8;
        gboff_c[t] = (uint32_t)(lrow * Hh + lseg * 8);
    }

    // ---- ldsm address bases ----
    uint32_t abase[2], axr[2], bbase[4], bxr[4];
    {
        const int aseg0 = lane >> 4;
        const int bseg0 = (lane >> 3) & 1;
#pragma unroll
        for (int mt = 0; mt < 2; ++mt) {
            int r = wm * 32 + mt * 16 + (lane & 15);
            abase[mt] = (uint32_t)(r * 128 + ((aseg0 ^ (r & 1)) << 4));
            axr[mt] = (uint32_t)(r & 6);
        }
#pragma unroll
        for (int np = 0; np < 4; ++np) {
            int r = wn * 64 + np * 16 + ((lane >> 4) << 3) + (lane & 7);
            bbase[np] = (uint32_t)(r * 128 + ((bseg0 ^ (r & 1)) << 4));
            bxr[np] = (uint32_t)(r & 6);
        }
    }
    const uint32_t ksrot = (uint32_t)(wn << 1);

    auto fill = [&](int cc2) {
        const int s2 = cc2 % NSTAGE;
        const uint32_t base = sb + SM_STG + (uint32_t)s2 * STAGE_BYTES;
        const int kb = (cc2 & 15) * 64;
        const uint32_t jb = (uint32_t)((cc2 >> 4) * 128) * Hh;
#pragma unroll
        for (int t = 0; t < 4; ++t) cp_async16(base + ldst[t], g_Ehc + gaoff[t] + kb);
#pragma unroll
        for (int t = 0; t < 4; ++t)
            cp_async16(base + A_BYTES + ldst[t], g_Bh + jb + gboff_c[t] + kb);
        CP_ASYNC_MBAR_ARRIVE_NOINC(sb + SM_MBAR + s2 * 16);
    };

    if (tid == 0) {
#pragma unroll
        for (int s = 0; s < NSTAGE; ++s) {
            MBAR_INIT(sb + SM_MBAR + s * 16, 256);
            MBAR_INIT(sb + SM_MBAR + s * 16 + 8, 256);
        }
    }
    if (tid < 128) {
        ((float*)(smem + SM_DH))[tid] = dh_sum((n0 << 10) + tid);
        ((float*)(smem + SM_V))[tid] = v[tid];
    } else {
        ((float*)(smem + SM_DH))[tid] = dh_sum((n1 << 10) + (tid - 128));
    }
    __syncthreads();

    float acc[2][8][4];
#pragma unroll
    for (int mt = 0; mt < 2; ++mt)
#pragma unroll
        for (int nt = 0; nt < 8; ++nt)
#pragma unroll
            for (int e = 0; e < 4; ++e) acc[mt][nt][e] = 0.f;

    fill(0);
    fill(1);

    for (int cc = 0; cc < 128; ++cc) {
        const int s = cc % NSTAGE;
        MBAR_WAIT_PARITY(sb + SM_MBAR + s * 16, (cc / 3) & 1);

        const uint32_t base = sb + SM_STG + (uint32_t)s * STAGE_BYTES;
        const uint32_t sA = base;
        const uint32_t sB = base + A_BYTES;

#pragma unroll
        for (int ks = 0; ks < 4; ++ks) {
            const uint32_t ksx = (uint32_t)(((ks + ksrot) & 3) * 2);
            uint32_t ah[2][4];
            ldsm_x4(ah[0], sA + abase[0] + ((ksx ^ axr[0]) << 4));
            ldsm_x4(ah[1], sA + abase[1] + ((ksx ^ axr[1]) << 4));
            uint32_t bb[2][4];
            ldsm_x4(bb[0], sB + bbase[0] + ((ksx ^ bxr[0]) << 4));
#pragma unroll
            for (int np = 0; np < 4; ++np) {
                if (np < 3)
                    ldsm_x4(bb[(np + 1) & 1], sB + bbase[np + 1] + ((ksx ^ bxr[np + 1]) << 4));
                const uint32_t* bq = bb[np & 1];
                mma_f16(acc[0][np * 2 + 0], ah[0], bq[0], bq[1]);
                mma_f16(acc[0][np * 2 + 1], ah[0], bq[2], bq[3]);
                mma_f16(acc[1][np * 2 + 0], ah[1], bq[0], bq[1]);
                mma_f16(acc[1][np * 2 + 1], ah[1], bq[2], bq[3]);
            }
        }
        MBAR_ARRIVE(sb + SM_MBAR + s * 16 + 8);

        const int c2 = cc + 2;
        if (c2 < 128) {
            const int s2 = c2 % NSTAGE;
            if (c2 >= NSTAGE)
                MBAR_WAIT_PARITY(sb + SM_MBAR + s2 * 16 + 8, (c2 / 3 - 1) & 1);
            fill(c2);
        }

        if ((cc & 15) == 15) {
            const int jglob = cc >> 4;          // 0..7
            const int jb1 = jglob & 1;
            if (jglob < 7) {
                if (tid < 128) {
                    ((float*)(smem + SM_DH + (1 - jb1) * 1024))[tid] =
                        dh_sum((n0 << 10) + (jglob + 1) * 128 + tid);
                    ((float*)(smem + SM_V + (1 - jb1) * 512))[tid] =
                        v[(jglob + 1) * 128 + tid];
                } else {
                    ((float*)(smem + SM_DH + (1 - jb1) * 1024))[tid] =
                        dh_sum((n1 << 10) + (jglob + 1) * 128 + (tid - 128));
                }
            }
            const float* dhb = (const float*)(smem + SM_DH + jb1 * 1024);
            const float* vs = (const float*)(smem + SM_V + jb1 * 512);
            const float* dsel[2][2];
#pragma unroll
            for (int mt = 0; mt < 2; ++mt)
#pragma unroll
                for (int rh = 0; rh < 2; ++rh) {
                    int rl = wm * 32 + mt * 16 + (lane >> 2) + rh * 8;
                    dsel[mt][rh] = (rl >= bl) ? (dhb + 128) : dhb;
                }
            float part[4] = {0.f, 0.f, 0.f, 0.f};
#pragma unroll
            for (int mt = 0; mt < 2; ++mt)
#pragma unroll
                for (int nt = 0; nt < 8; ++nt)
#pragma unroll
                    for (int e = 0; e < 4; ++e) {
                        int col = wn * 64 + nt * 8 + (lane & 3) * 2 + (e & 1);
                        part[mt * 2 + (e >> 1)] +=
                            tanh_fast(acc[mt][nt][e] + dsel[mt][e >> 1][col]) * vs[col];
                        acc[mt][nt][e] = 0.f;
                    }
#pragma unroll
            for (int p = 0; p < 4; ++p) {
                part[p] += __shfl_xor_sync(0xffffffffu, part[p], 1);
                part[p] += __shfl_xor_sync(0xffffffffu, part[p], 2);
            }
            float* sred = (float*)(smem + SM_SRED);
            __syncthreads();
            if ((lane & 3) == 0) {
#pragma unroll
                for (int mt = 0; mt < 2; ++mt)
#pragma unroll
                    for (int rr = 0; rr < 2; ++rr) {
                        int row = wm * 32 + mt * 16 + (lane >> 2) + rr * 8;
                        sred[row * 2 + wn] = part[mt * 2 + rr];
                    }
            }
            __syncthreads();
            if (tid < 128)
                g_scorePC[jglob][row0c + tid] = sred[tid * 2] + sred[tid * 2 + 1];
        }
    }
}

// ---------------------------------------------------------------------------
// Context with inline softmax over GLOBAL compact rows of this n.
// ---------------------------------------------------------------------------
__global__ __launch_bounds__(128) void context_kernel(float* __restrict__ attn) {
    __shared__ float sa[256];
    __shared__ float red[128];
    const int n = blockIdx.x, lc = blockIdx.y;
    const int tid = threadIdx.x;
    const int cnt = g_cnt[n];
    const int gbase = g_off[n];

    float s[8];
    float pv[8];
    float lmax = -CUDART_INF_F;
#pragma unroll
    for (int q = 0; q < 8; ++q) {
        int r = tid + 128 * q;
        float a = 0.f;
        if (r < cnt) {
#pragma unroll
            for (int p = 0; p < 8; ++p) a += g_scorePC[p][gbase + r];
            lmax = fmaxf(lmax, a);
        }
        s[q] = a;
    }
    red[tid] = lmax;
    __syncthreads();
    for (int o = 64; o; o >>= 1) {
        if (tid < o) red[tid] = fmaxf(red[tid], red[tid + o]);
        __syncthreads();
    }
    const float mx = red[0];
    __syncthreads();
    float lsum = 0.f;
#pragma unroll
    for (int q = 0; q < 8; ++q) {
        int r = tid + 128 * q;
        pv[q] = (r < cnt) ? __expf(s[q] - mx) : 0.f;
        lsum += pv[q];
    }
    red[tid] = lsum;
    __syncthreads();
    for (int o = 64; o; o >>= 1) {
        if (tid < o) red[tid] += red[tid + o];
        __syncthreads();
    }
    const float inv = 1.0f / red[0];
    __syncthreads();

#pragma unroll
    for (int qq = 0; qq < 2; ++qq) {
        int q = 2 * lc + qq;
        int r = tid + 128 * q;
        int i = tid + 128 * qq;
        float w = 0.f;
        if (r < cnt) {
            int l = g_gidx[(n << 10) + r];
            w = pv[q] * inv;
            attn[(n << 10) + l] = w;
        }
        sa[i] = w;
    }
    __syncthreads();

    const int lim = min(256, cnt - lc * 256);
    const uint4* Ep = (const uint4*)(g_Ehc + (size_t)(gbase + lc * 256) * Hh) + tid;
    float acc[8] = {};
#pragma unroll 4
    for (int i = 0; i < lim; ++i) {
        uint4 u = Ep[(size_t)i * 128];
        const __half2* h2 = (const __half2*)&u;
        float a = sa[i];
#pragma unroll
        for (int q = 0; q < 4; ++q) {
            float2 f = __half22float2(h2[q]);
            acc[q * 2 + 0] += a * f.x;
            acc[q * 2 + 1] += a * f.y;
        }
    }
    float4* dst = &g_ctxP4[lc][n * 256 + tid * 2];
    dst[0] = make_float4(acc[0], acc[1], acc[2], acc[3]);
    dst[1] = make_float4(acc[4], acc[5], acc[6], acc[7]);
}

__global__ __launch_bounds__(256) void ctx_reduce_kernel(float4* __restrict__ ctx4) {
    int i = blockIdx.x * 256 + threadIdx.x;
    float4 a = g_ctxP4[0][i], b = g_ctxP4[1][i], c = g_ctxP4[2][i], d = g_ctxP4[3][i];
    ctx4[i] = make_float4(a.x + b.x + c.x + d.x, a.y + b.y + c.y + d.y,
                          a.z + b.z + c.z + d.z, a.w + b.w + c.w + d.w);
}

// ---------------------------------------------------------------------------
extern "C" void kernel_launch(void* const* d_in, const int* in_sizes, int n_in,
                              void* d_out, int out_size) {
    const float* dec  = (const float*)d_in[0];
    const float* E    = (const float*)d_in[1];
    const int*   mask = (const int*)  d_in[2];
    const float* Wh   = (const float*)d_in[3];
    const float* Ws   = (const float*)d_in[4];
    const float* v    = (const float*)d_in[5];

    float* out  = (float*)d_out;
    float* ctx  = out;
    float* attn = out + Nn * Hh;

    cudaFuncSetAttribute(score_kernel, cudaFuncAttributeMaxDynamicSharedMemorySize, SM_TOTAL);

    bconv_kernel<<<(Hh * Hh / 8) / 256, 256>>>(Ws);
    compact_kernel<<<Nn, 256>>>(mask, attn);
    scan_kernel<<<1, 32>>>();
    econvc_kernel<<<dim3(Nn, 8), 256>>>(E);
    dh_kernel<<<128, 256>>>(dec, Wh);
    score_kernel<<<512, 256, SM_TOTAL>>>(v);
    context_kernel<<<dim3(Nn, 4), 128>>>(attn);
    ctx_reduce_kernel<<<(Nn * Hh / 4) / 256, 256>>>((float4*)ctx);
}

// round 16
// speedup vs baseline: 1.1571x; 1.0841x over previous
#include <cuda_runtime.h>
#include <cuda_fp16.h>
#include <math_constants.h>
#include <cstdint>

#define Nn 64
#define Ll 1024
#define Hh 1024

// ---------------------------------------------------------------------------
// Device scratch
// ---------------------------------------------------------------------------
__device__ float g_dhP[8][Nn * Hh];
__device__ float g_scorePC[8][Nn * Ll];
__device__ int   g_gidx[Nn * Ll];
__device__ int   g_cnt[Nn];
__device__ int   g_off[Nn + 1];
__device__ int   g_done;                  // compact completion ticket (self-resets)
__device__ __align__(16) __half g_Bh[Hh * Hh];
__device__ __align__(16) __half g_Ehc[Nn * Ll * Hh];
__device__ float4 g_ctxP8[8][Nn * (Hh / 4)];

// ---------------------------------------------------------------------------
// Helpers
// ---------------------------------------------------------------------------
__device__ __forceinline__ uint32_t smem_u32(const void* p) {
    uint32_t a;
    asm("{ .reg .u64 t; cvta.to.shared.u64 t, %1; cvt.u32.u64 %0, t; }" : "=r"(a) : "l"(p));
    return a;
}
__device__ __forceinline__ float tanh_fast(float x) {
    float e = __expf(2.0f * x);
    return 1.0f - __fdividef(2.0f, e + 1.0f);
}
__device__ __forceinline__ void ldsm_x4(uint32_t* r, uint32_t addr) {
    asm volatile("ldmatrix.sync.aligned.m8n8.x4.shared.b16 {%0,%1,%2,%3}, [%4];"
                 : "=r"(r[0]), "=r"(r[1]), "=r"(r[2]), "=r"(r[3]) : "r"(addr));
}
__device__ __forceinline__ void mma_f16(float* c, const uint32_t* a, uint32_t b0, uint32_t b1) {
    asm volatile("mma.sync.aligned.m16n8k16.row.col.f32.f16.f16.f32 "
                 "{%0,%1,%2,%3}, {%4,%5,%6,%7}, {%8,%9}, {%0,%1,%2,%3};"
                 : "+f"(c[0]), "+f"(c[1]), "+f"(c[2]), "+f"(c[3])
                 : "r"(a[0]), "r"(a[1]), "r"(a[2]), "r"(a[3]), "r"(b0), "r"(b1));
}
__device__ __forceinline__ void cp_async16(uint32_t dst, const void* src) {
    asm volatile("cp.async.cg.shared.global [%0], [%1], 16;" :: "r"(dst), "l"(src) : "memory");
}

// ---- mbarrier ops (generic PTX) ----
#define MBAR_INIT(addr, cnt) \
    asm volatile("mbarrier.init.shared.b64 [%0], %1;" :: "r"((uint32_t)(addr)), "r"((uint32_t)(cnt)) : "memory")
#define MBAR_ARRIVE(addr) \
    asm volatile("{\n\t.reg .b64 t;\n\tmbarrier.arrive.shared.b64 t, [%0];\n\t}" \
                 :: "r"((uint32_t)(addr)) : "memory")
#define CP_ASYNC_MBAR_ARRIVE_NOINC(addr) \
    asm volatile("cp.async.mbarrier.arrive.noinc.shared.b64 [%0];" :: "r"((uint32_t)(addr)) : "memory")
#define MBAR_WAIT_PARITY(addr, parity) do {                                              \
    uint32_t _mbar = (uint32_t)(addr);                                                   \
    uint32_t _par  = (uint32_t)(parity);                                                 \
    uint32_t _done;                                                                      \
    asm volatile("{\n\t.reg .pred p;\n\t"                                                \
        "mbarrier.try_wait.parity.acquire.cta.shared::cta.b64 p, [%1], %2;\n\t"          \
        "selp.b32 %0, 1, 0, p;\n\t}" : "=r"(_done) : "r"(_mbar), "r"(_par) : "memory");  \
    if (!_done) {                                                                        \
        asm volatile("{\n\t.reg .pred P1;\n\t"                                           \
            "WL_%=:\n\t"                                                                 \
            "mbarrier.try_wait.parity.acquire.cta.shared::cta.b64 P1, [%0], %1, 0x989680;\n\t" \
            "@P1 bra.uni WD_%=;\n\t"                                                     \
            "bra.uni WL_%=;\n\t"                                                         \
            "WD_%=:\n\t}" :: "r"(_mbar), "r"(_par) : "memory");                          \
    }                                                                                    \
} while (0)

// ---------------------------------------------------------------------------
// prep: blocks 0..511 = Ws->fp16 conversion; blocks 512..575 = mask compact
// (+ last compact block runs the offset scan).
// ---------------------------------------------------------------------------
__global__ __launch_bounds__(256) void prep_kernel(const float* __restrict__ Ws,
                                                   const int* __restrict__ mask,
                                                   float* __restrict__ attn) {
    const int tid = threadIdx.x;
    if (blockIdx.x < 512) {
        size_t i = (size_t)blockIdx.x * 256 + tid;
        float4 w0 = ((const float4*)Ws)[2 * i];
        float4 w1 = ((const float4*)Ws)[2 * i + 1];
        __half2 h[4];
        h[0] = __floats2half2_rn(w0.x, w0.y);
        h[1] = __floats2half2_rn(w0.z, w0.w);
        h[2] = __floats2half2_rn(w1.x, w1.y);
        h[3] = __floats2half2_rn(w1.z, w1.w);
        ((uint4*)g_Bh)[i] = *(uint4*)h;
        return;
    }
    // --- compact part ---
    __shared__ int sc[256];
    const int n = blockIdx.x - 512;
    int m[4];
    int c = 0;
#pragma unroll
    for (int q = 0; q < 4; ++q) {
        m[q] = mask[(n << 10) + tid * 4 + q];
        if (!m[q]) ++c;
        attn[(n << 10) + tid * 4 + q] = 0.f;
    }
    sc[tid] = c;
    __syncthreads();
    for (int off = 1; off < 256; off <<= 1) {
        int vv = (tid >= off) ? sc[tid - off] : 0;
        __syncthreads();
        sc[tid] += vv;
        __syncthreads();
    }
    int base = sc[tid] - c;
    if (tid == 255) g_cnt[n] = sc[255];
#pragma unroll
    for (int q = 0; q < 4; ++q)
        if (!m[q]) g_gidx[(n << 10) + base++] = tid * 4 + q;
    __syncthreads();
    if (tid == 0) {
        __threadfence();
        int t = atomicAdd(&g_done, 1);
        if (t == Nn - 1) {
            __threadfence();
            int acc = 0;
            for (int i = 0; i < Nn; ++i) {
                g_off[i] = acc;
                acc += g_cnt[i];
            }
            g_off[Nn] = acc;
            g_done = 0;  // reset for next graph replay
            __threadfence();
        }
    }
}

// ---------------------------------------------------------------------------
// Convert unmasked E rows -> GLOBAL compact fp16. grid (64, 8, 2):
// z = column half (64 u4 cols). Indices staged in smem; MLP 8.
// ---------------------------------------------------------------------------
__global__ __launch_bounds__(256) void econvc_kernel(const float* __restrict__ E) {
    __shared__ int sgl[128];
    const int n = blockIdx.x;
    const int row0 = blockIdx.y * 128;
    const int cnt = g_cnt[n];
    if (row0 >= cnt) return;
    const int tid = threadIdx.x;
    const int lim = min(128, cnt - row0);
    const int gbase = g_off[n] + row0;

    if (tid < 128)
        sgl[tid] = (tid < lim) ? g_gidx[(n << 10) + row0 + tid] : 0;
    __syncthreads();

    const int u = (tid & 63) + blockIdx.z * 64;   // uint4 col
    const int r0 = tid >> 6;                      // 0..3, rows stride 4
    const float4* __restrict__ Ebase = (const float4*)(E + (size_t)(n << 10) * Hh);

#pragma unroll 1
    for (int k = 0; k < 32; k += 4) {
        int rr[4];
        float4 w0[4], w1[4];
#pragma unroll
        for (int q = 0; q < 4; ++q) {
            rr[q] = r0 + 4 * (k + q);
            if (rr[q] < lim) {
                const float4* src = Ebase + (size_t)sgl[rr[q]] * 256 + u * 2;
                w0[q] = src[0];
                w1[q] = src[1];
            }
        }
#pragma unroll
        for (int q = 0; q < 4; ++q) {
            if (rr[q] < lim) {
                __half2 h[4];
                h[0] = __floats2half2_rn(w0[q].x, w0[q].y);
                h[1] = __floats2half2_rn(w0[q].z, w0[q].w);
                h[2] = __floats2half2_rn(w1[q].x, w1[q].y);
                h[3] = __floats2half2_rn(w1[q].z, w1[q].w);
                ((uint4*)(g_Ehc + (size_t)(gbase + rr[q]) * Hh))[u] = *(uint4*)h;
            }
        }
    }
}

// ---------------------------------------------------------------------------
// dh partials: tiled GEMM. grid 128 = 16 k-blocks x 8 h-splits.
// ---------------------------------------------------------------------------
__global__ __launch_bounds__(256) void dh_kernel(const float* __restrict__ dec,
                                                 const float* __restrict__ Wh) {
    __shared__ float ds[64][68];
    __shared__ float ws[64][68];
    const int tid = threadIdx.x;
    const int kb = (blockIdx.x & 15) * 64;
    const int hs = blockIdx.x >> 4;
    const int n0 = (tid & 15) * 4;
    const int k0 = (tid >> 4) * 4;
    float acc[4][4] = {};
    for (int cc = 0; cc < 2; ++cc) {
        const int hb = hs * 128 + cc * 64;
        __syncthreads();
#pragma unroll
        for (int q = 0; q < 4; ++q) {
            int f4 = tid + 256 * q;
            int r = f4 >> 4;
            int col = f4 & 15;
            float4 a = *(const float4*)(dec + (size_t)r * Hh + hb + col * 4);
            ds[col * 4 + 0][r] = a.x; ds[col * 4 + 1][r] = a.y;
            ds[col * 4 + 2][r] = a.z; ds[col * 4 + 3][r] = a.w;
            float4 b = *(const float4*)(Wh + (size_t)(kb + r) * Hh + hb + col * 4);
            ws[col * 4 + 0][r] = b.x; ws[col * 4 + 1][r] = b.y;
            ws[col * 4 + 2][r] = b.z; ws[col * 4 + 3][r] = b.w;
        }
        __syncthreads();
#pragma unroll 8
        for (int h = 0; h < 64; ++h) {
            float a[4], b[4];
            *(float4*)a = *(const float4*)&ds[h][n0];
            *(float4*)b = *(const float4*)&ws[h][k0];
#pragma unroll
            for (int i = 0; i < 4; ++i)
#pragma unroll
                for (int j = 0; j < 4; ++j) acc[i][j] += a[i] * b[j];
        }
    }
#pragma unroll
    for (int i = 0; i < 4; ++i)
#pragma unroll
        for (int j = 0; j < 4; ++j)
            g_dhP[hs][(n0 + i) * Hh + kb + k0 + j] = acc[i][j];
}

__device__ __forceinline__ float dh_sum(int idx) {
    float a = 0.f;
#pragma unroll
    for (int p = 0; p < 8; ++p) a += g_dhP[p][idx];
    return a;
}

// ---------------------------------------------------------------------------
// Fused score kernel on GLOBAL compact rows, ALL 8 j-blocks per CTA (R15).
// ---------------------------------------------------------------------------
#define A_BYTES 16384
#define STAGE_BYTES (2 * A_BYTES)
#define NSTAGE 3
#define SM_DH   0
#define SM_V    2048
#define SM_SRED 3072
#define SM_MBAR 4096
#define SM_STG  5120
#define SM_TOTAL (SM_STG + NSTAGE * STAGE_BYTES)  // 103424

__global__ __launch_bounds__(256, 2) void score_kernel(const float* __restrict__ v) {
    const int row0c = blockIdx.x * 128;
    if (row0c >= g_off[Nn]) return;

    extern __shared__ char smem[];
    const uint32_t sb = smem_u32(smem);
    const int tid = threadIdx.x;
    const int lane = tid & 31;
    const int wid = tid >> 5;
    const int wm = wid & 3;
    const int wn = wid >> 2;

    int n0 = 0, n1 = 0;
    for (int m = 1; m < Nn; ++m) {
        int o = g_off[m];
        if (o <= row0c) n0 = m;
        if (o <= row0c + 127) n1 = m;
    }
    const int bl = g_off[n1] - row0c;

    uint32_t ldst[4];
    size_t gaoff[4];
    uint32_t gboff_c[4];
#pragma unroll
    for (int t = 0; t < 4; ++t) {
        int u = tid + 256 * t;
        int lrow = u >> 3, lseg = u & 7;
        ldst[t] = (uint32_t)(lrow * 128 + ((lseg ^ (lrow & 7)) << 4));
        gaoff[t] = (size_t)(row0c + lrow) * Hh + lseg * 8;
        gboff_c[t] = (uint32_t)(lrow * Hh + lseg * 8);
    }

    uint32_t abase[2], axr[2], bbase[4], bxr[4];
    {
        const int aseg0 = lane >> 4;
        const int bseg0 = (lane >> 3) & 1;
#pragma unroll
        for (int mt = 0; mt < 2; ++mt) {
            int r = wm * 32 + mt * 16 + (lane & 15);
            abase[mt] = (uint32_t)(r * 128 + ((aseg0 ^ (r & 1)) << 4));
            axr[mt] = (uint32_t)(r & 6);
        }
#pragma unroll
        for (int np = 0; np < 4; ++np) {
            int r = wn * 64 + np * 16 + ((lane >> 4) << 3) + (lane & 7);
            bbase[np] = (uint32_t)(r * 128 + ((bseg0 ^ (r & 1)) << 4));
            bxr[np] = (uint32_t)(r & 6);
        }
    }
    const uint32_t ksrot = (uint32_t)(wn << 1);

    auto fill = [&](int cc2) {
        const int s2 = cc2 % NSTAGE;
        const uint32_t base = sb + SM_STG + (uint32_t)s2 * STAGE_BYTES;
        const int kb = (cc2 & 15) * 64;
        const uint32_t jb = (uint32_t)((cc2 >> 4) * 128) * Hh;
#pragma unroll
        for (int t = 0; t < 4; ++t) cp_async16(base + ldst[t], g_Ehc + gaoff[t] + kb);
#pragma unroll
        for (int t = 0; t < 4; ++t)
            cp_async16(base + A_BYTES + ldst[t], g_Bh + jb + gboff_c[t] + kb);
        CP_ASYNC_MBAR_ARRIVE_NOINC(sb + SM_MBAR + s2 * 16);
    };

    if (tid == 0) {
#pragma unroll
        for (int s = 0; s < NSTAGE; ++s) {
            MBAR_INIT(sb + SM_MBAR + s * 16, 256);
            MBAR_INIT(sb + SM_MBAR + s * 16 + 8, 256);
        }
    }
    if (tid < 128) {
        ((float*)(smem + SM_DH))[tid] = dh_sum((n0 << 10) + tid);
        ((float*)(smem + SM_V))[tid] = v[tid];
    } else {
        ((float*)(smem + SM_DH))[tid] = dh_sum((n1 << 10) + (tid - 128));
    }
    __syncthreads();

    float acc[2][8][4];
#pragma unroll
    for (int mt = 0; mt < 2; ++mt)
#pragma unroll
        for (int nt = 0; nt < 8; ++nt)
#pragma unroll
            for (int e = 0; e < 4; ++e) acc[mt][nt][e] = 0.f;

    fill(0);
    fill(1);

    for (int cc = 0; cc < 128; ++cc) {
        const int s = cc % NSTAGE;
        MBAR_WAIT_PARITY(sb + SM_MBAR + s * 16, (cc / 3) & 1);

        const uint32_t base = sb + SM_STG + (uint32_t)s * STAGE_BYTES;
        const uint32_t sA = base;
        const uint32_t sB = base + A_BYTES;

#pragma unroll
        for (int ks = 0; ks < 4; ++ks) {
            const uint32_t ksx = (uint32_t)(((ks + ksrot) & 3) * 2);
            uint32_t ah[2][4];
            ldsm_x4(ah[0], sA + abase[0] + ((ksx ^ axr[0]) << 4));
            ldsm_x4(ah[1], sA + abase[1] + ((ksx ^ axr[1]) << 4));
            uint32_t bb[2][4];
            ldsm_x4(bb[0], sB + bbase[0] + ((ksx ^ bxr[0]) << 4));
#pragma unroll
            for (int np = 0; np < 4; ++np) {
                if (np < 3)
                    ldsm_x4(bb[(np + 1) & 1], sB + bbase[np + 1] + ((ksx ^ bxr[np + 1]) << 4));
                const uint32_t* bq = bb[np & 1];
                mma_f16(acc[0][np * 2 + 0], ah[0], bq[0], bq[1]);
                mma_f16(acc[0][np * 2 + 1], ah[0], bq[2], bq[3]);
                mma_f16(acc[1][np * 2 + 0], ah[1], bq[0], bq[1]);
                mma_f16(acc[1][np * 2 + 1], ah[1], bq[2], bq[3]);
            }
        }
        MBAR_ARRIVE(sb + SM_MBAR + s * 16 + 8);

        const int c2 = cc + 2;
        if (c2 < 128) {
            const int s2 = c2 % NSTAGE;
            if (c2 >= NSTAGE)
                MBAR_WAIT_PARITY(sb + SM_MBAR + s2 * 16 + 8, (c2 / 3 - 1) & 1);
            fill(c2);
        }

        if ((cc & 15) == 15) {
            const int jglob = cc >> 4;
            const int jb1 = jglob & 1;
            if (jglob < 7) {
                if (tid < 128) {
                    ((float*)(smem + SM_DH + (1 - jb1) * 1024))[tid] =
                        dh_sum((n0 << 10) + (jglob + 1) * 128 + tid);
                    ((float*)(smem + SM_V + (1 - jb1) * 512))[tid] =
                        v[(jglob + 1) * 128 + tid];
                } else {
                    ((float*)(smem + SM_DH + (1 - jb1) * 1024))[tid] =
                        dh_sum((n1 << 10) + (jglob + 1) * 128 + (tid - 128));
                }
            }
            const float* dhb = (const float*)(smem + SM_DH + jb1 * 1024);
            const float* vs = (const float*)(smem + SM_V + jb1 * 512);
            const float* dsel[2][2];
#pragma unroll
            for (int mt = 0; mt < 2; ++mt)
#pragma unroll
                for (int rh = 0; rh < 2; ++rh) {
                    int rl = wm * 32 + mt * 16 + (lane >> 2) + rh * 8;
                    dsel[mt][rh] = (rl >= bl) ? (dhb + 128) : dhb;
                }
            float part[4] = {0.f, 0.f, 0.f, 0.f};
#pragma unroll
            for (int mt = 0; mt < 2; ++mt)
#pragma unroll
                for (int nt = 0; nt < 8; ++nt)
#pragma unroll
                    for (int e = 0; e < 4; ++e) {
                        int col = wn * 64 + nt * 8 + (lane & 3) * 2 + (e & 1);
                        part[mt * 2 + (e >> 1)] +=
                            tanh_fast(acc[mt][nt][e] + dsel[mt][e >> 1][col]) * vs[col];
                        acc[mt][nt][e] = 0.f;
                    }
#pragma unroll
            for (int p = 0; p < 4; ++p) {
                part[p] += __shfl_xor_sync(0xffffffffu, part[p], 1);
                part[p] += __shfl_xor_sync(0xffffffffu, part[p], 2);
            }
            float* sred = (float*)(smem + SM_SRED);
            __syncthreads();
            if ((lane & 3) == 0) {
#pragma unroll
                for (int mt = 0; mt < 2; ++mt)
#pragma unroll
                    for (int rr = 0; rr < 2; ++rr) {
                        int row = wm * 32 + mt * 16 + (lane >> 2) + rr * 8;
                        sred[row * 2 + wn] = part[mt * 2 + rr];
                    }
            }
            __syncthreads();
            if (tid < 128)
                g_scorePC[jglob][row0c + tid] = sred[tid * 2] + sred[tid * 2 + 1];
        }
    }
}

// ---------------------------------------------------------------------------
// Context with inline softmax; grid (n, 8 chunks of 128 compact rows).
// Out-of-range chunks write zero partials (no early return before store).
// ---------------------------------------------------------------------------
__global__ __launch_bounds__(128) void context_kernel(float* __restrict__ attn) {
    __shared__ float sa[128];
    __shared__ float red[128];
    const int n = blockIdx.x, lc = blockIdx.y;
    const int tid = threadIdx.x;
    const int cnt = g_cnt[n];
    const int gbase = g_off[n];

    float s[8];
    float pv[8];
    float lmax = -CUDART_INF_F;
#pragma unroll
    for (int q = 0; q < 8; ++q) {
        int r = tid + 128 * q;
        float a = 0.f;
        if (r < cnt) {
#pragma unroll
            for (int p = 0; p < 8; ++p) a += g_scorePC[p][gbase + r];
            lmax = fmaxf(lmax, a);
        }
        s[q] = a;
    }
    red[tid] = lmax;
    __syncthreads();
    for (int o = 64; o; o >>= 1) {
        if (tid < o) red[tid] = fmaxf(red[tid], red[tid + o]);
        __syncthreads();
    }
    const float mx = red[0];
    __syncthreads();
    float lsum = 0.f;
#pragma unroll
    for (int q = 0; q < 8; ++q) {
        int r = tid + 128 * q;
        pv[q] = (r < cnt) ? __expf(s[q] - mx) : 0.f;
        lsum += pv[q];
    }
    red[tid] = lsum;
    __syncthreads();
    for (int o = 64; o; o >>= 1) {
        if (tid < o) red[tid] += red[tid + o];
        __syncthreads();
    }
    const float inv = 1.0f / red[0];
    __syncthreads();

    // our chunk = rows [lc*128, lc*128+128); each thread owns row lc*128+tid
    {
        int r = lc * 128 + tid;
        float w = 0.f;
        if (r < cnt) {
            int l = g_gidx[(n << 10) + r];
            w = pv[lc] * inv;
            attn[(n << 10) + l] = w;
        }
        sa[tid] = w;
    }
    __syncthreads();

    const int lim = min(128, cnt - lc * 128);
    const uint4* Ep = (const uint4*)(g_Ehc + (size_t)(gbase + lc * 128) * Hh) + tid;
    float acc[8] = {};
#pragma unroll 4
    for (int i = 0; i < lim; ++i) {
        uint4 u = Ep[(size_t)i * 128];
        const __half2* h2 = (const __half2*)&u;
        float a = sa[i];
#pragma unroll
        for (int q = 0; q < 4; ++q) {
            float2 f = __half22float2(h2[q]);
            acc[q * 2 + 0] += a * f.x;
            acc[q * 2 + 1] += a * f.y;
        }
    }
    float4* dst = &g_ctxP8[lc][n * 256 + tid * 2];
    dst[0] = make_float4(acc[0], acc[1], acc[2], acc[3]);
    dst[1] = make_float4(acc[4], acc[5], acc[6], acc[7]);
}

__global__ __launch_bounds__(256) void ctx_reduce_kernel(float4* __restrict__ ctx4) {
    int i = blockIdx.x * 256 + threadIdx.x;
    float4 r = make_float4(0.f, 0.f, 0.f, 0.f);
#pragma unroll
    for (int p = 0; p < 8; ++p) {
        float4 a = g_ctxP8[p][i];
        r.x += a.x; r.y += a.y; r.z += a.z; r.w += a.w;
    }
    ctx4[i] = r;
}

// ---------------------------------------------------------------------------
extern "C" void kernel_launch(void* const* d_in, const int* in_sizes, int n_in,
                              void* d_out, int out_size) {
    const float* dec  = (const float*)d_in[0];
    const float* E    = (const float*)d_in[1];
    const int*   mask = (const int*)  d_in[2];
    const float* Wh   = (const float*)d_in[3];
    const float* Ws   = (const float*)d_in[4];
    const float* v    = (const float*)d_in[5];

    float* out  = (float*)d_out;
    float* ctx  = out;
    float* attn = out + Nn * Hh;

    cudaFuncSetAttribute(score_kernel, cudaFuncAttributeMaxDynamicSharedMemorySize, SM_TOTAL);

    prep_kernel<<<576, 256>>>(Ws, mask, attn);
    econvc_kernel<<<dim3(Nn, 8, 2), 256>>>(E);
    dh_kernel<<<128, 256>>>(dec, Wh);
    score_kernel<<<512, 256, SM_TOTAL>>>(v);
    context_kernel<<<dim3(Nn, 8), 128>>>(attn);
    ctx_reduce_kernel<<<(Nn * Hh / 4) / 256, 256>>>((float4*)ctx);
}